// round 8
// baseline (speedup 1.0000x reference)
#include <cuda_runtime.h>

static constexpr int H = 512;
static constexpr int W = 512;
static constexpr unsigned FULL = 0xFFFFFFFFu;

__device__ __forceinline__ float med3f(float a, float b, float c) {
    return fmaxf(fminf(a, b), fminf(fmaxf(a, b), c));
}

// Horizontal merge for 4 outputs of one row.
// lo/md/hi: [L-edge, 4 own columns, R-edge] (6 entries), each vertically sorted.
// Pair (2k+1, 2k+2) is shared by windows 2k and 2k+1.
__device__ __forceinline__ void hmerge4(const float* lo, const float* md,
                                         const float* hi, float* o) {
#pragma unroll
    for (int k = 0; k < 2; k++) {
        float pxl = fmaxf(lo[2 * k + 1], lo[2 * k + 2]);
        float pzl = fminf(hi[2 * k + 1], hi[2 * k + 2]);
        float mn  = fminf(md[2 * k + 1], md[2 * k + 2]);
        float mx  = fmaxf(md[2 * k + 1], md[2 * k + 2]);
        float X0 = fmaxf(lo[2 * k], pxl);
        float X1 = fmaxf(pxl, lo[2 * k + 3]);
        float Z0 = fminf(hi[2 * k], pzl);
        float Z1 = fminf(pzl, hi[2 * k + 3]);
        float Y0 = fmaxf(mn, fminf(mx, md[2 * k]));
        float Y1 = fmaxf(mn, fminf(mx, md[2 * k + 3]));
        o[2 * k]     = med3f(X0, Y0, Z0);
        o[2 * k + 1] = med3f(X1, Y1, Z1);
    }
}

// Merge row t into pre-sorted pair (p,q), exchange edge triples, merge, store one row.
__device__ __forceinline__ void do_row(const float* t, const float* p, const float* q,
                                        float et, float ep, float eq,
                                        bool isL, bool isR,
                                        float* __restrict__ orow, int c0) {
    float lo[6], md[6], hi[6];
#pragma unroll
    for (int i = 0; i < 4; i++) {
        float m = fmaxf(t[i], p[i]);
        lo[i + 1] = fminf(t[i], p[i]);
        hi[i + 1] = fmaxf(m, q[i]);
        md[i + 1] = fminf(m, q[i]);
    }
    float em = fmaxf(et, ep);
    float elo = fminf(et, ep), ehi = fmaxf(em, eq), emd = fminf(em, eq);
    float Ll = __shfl_up_sync(FULL, lo[4], 1);
    float Lm = __shfl_up_sync(FULL, md[4], 1);
    float Lh = __shfl_up_sync(FULL, hi[4], 1);
    float Rl = __shfl_down_sync(FULL, lo[1], 1);
    float Rm = __shfl_down_sync(FULL, md[1], 1);
    float Rh = __shfl_down_sync(FULL, hi[1], 1);
    lo[0] = isL ? elo : Ll;  md[0] = isL ? emd : Lm;  hi[0] = isL ? ehi : Lh;
    lo[5] = isR ? elo : Rl;  md[5] = isR ? emd : Rm;  hi[5] = isR ? ehi : Rh;
    float o[4];
    hmerge4(lo, md, hi, o);
    *(float4*)(orow + c0) = make_float4(o[0], o[1], o[2], o[3]);
}

__global__ __launch_bounds__(128, 8)
void median3x3_kernel(const float* __restrict__ in, float* __restrict__ out, int nimg) {
    const int gwarp = (blockIdx.x * blockDim.x + threadIdx.x) >> 5;
    const int lane = threadIdx.x & 31;

    // Per image: 128 row-quads (4 output rows each) x 4 warp-column-groups (128 cols each).
    const int img = gwarp >> 9;
    if (img >= nimg) return;
    const int rem = gwarp & 511;
    const int y0 = (rem >> 2) << 2;                  // 0,4,...,508
    const int c0 = ((rem & 3) << 7) + (lane << 2);   // 4 columns per lane

    const float* __restrict__ base = in + (size_t)img * (H * W);
    float* __restrict__ obase = out + (size_t)img * (H * W);

    // ---- Load 6 input rows (y0-1 .. y0+4) x 4 cols: 6 x LDG.128 front-batched ----
    const float4 zero4 = make_float4(0.f, 0.f, 0.f, 0.f);
    const bool topOK = (y0 > 0);
    const bool botOK = (y0 + 4 < H);
    float4 i0 = topOK ? *(const float4*)(base + (y0 - 1) * W + c0) : zero4;
    float4 i1 =         *(const float4*)(base + (y0    ) * W + c0);
    float4 i2 =         *(const float4*)(base + (y0 + 1) * W + c0);
    float4 i3 =         *(const float4*)(base + (y0 + 2) * W + c0);
    float4 i4 =         *(const float4*)(base + (y0 + 3) * W + c0);
    float4 i5 = botOK ? *(const float4*)(base + (y0 + 4) * W + c0) : zero4;

    // Warp-edge boundary column (6 rows), lanes 0/31 only.
    const bool isL = (lane == 0);
    const bool isR = (lane == 31);
    const int ecol = isL ? (c0 - 1) : (c0 + 4);
    const bool ev = (isL | isR) && ((unsigned)ecol < (unsigned)W);
    float e0 = (ev && topOK) ? base[(y0 - 1) * W + ecol] : 0.f;
    float e1 = ev            ? base[(y0    ) * W + ecol] : 0.f;
    float e2 = ev            ? base[(y0 + 1) * W + ecol] : 0.f;
    float e3 = ev            ? base[(y0 + 2) * W + ecol] : 0.f;
    float e4 = ev            ? base[(y0 + 3) * W + ecol] : 0.f;
    float e5 = (ev && botOK) ? base[(y0 + 4) * W + ecol] : 0.f;

    float r2[4] = {i2.x, i2.y, i2.z, i2.w};
    float r3[4] = {i3.x, i3.y, i3.z, i3.w};

    // ---- Pair A = sort(i1, i2); i1 dies here ----
    float p[4], q[4];
    {
        float r1[4] = {i1.x, i1.y, i1.z, i1.w};
#pragma unroll
        for (int i = 0; i < 4; i++) {
            p[i] = fminf(r1[i], r2[i]);
            q[i] = fmaxf(r1[i], r2[i]);
        }
    }
    {
        const float epA = fminf(e1, e2), eqA = fmaxf(e1, e2);
        // Rows o0 = (i0, i1, i2), o1 = (i1, i2, i3) via shared pair A.
        float t0[4] = {i0.x, i0.y, i0.z, i0.w};
        do_row(t0, p, q, e0, epA, eqA, isL, isR, obase + (y0    ) * W, c0);
        do_row(r3, p, q, e3, epA, eqA, isL, isR, obase + (y0 + 1) * W, c0);
    }

    // ---- Pair B = sort(i3, i4); reuse p,q storage ----
    {
        float r4[4] = {i4.x, i4.y, i4.z, i4.w};
#pragma unroll
        for (int i = 0; i < 4; i++) {
            float mn = fminf(r3[i], r4[i]);
            float mx = fmaxf(r3[i], r4[i]);
            p[i] = mn;
            q[i] = mx;
        }
    }
    {
        const float epB = fminf(e3, e4), eqB = fmaxf(e3, e4);
        // Rows o2 = (i2, i3, i4), o3 = (i3, i4, i5) via shared pair B.
        do_row(r2, p, q, e2, epB, eqB, isL, isR, obase + (y0 + 2) * W, c0);
        float t5[4] = {i5.x, i5.y, i5.z, i5.w};
        do_row(t5, p, q, e5, epB, eqB, isL, isR, obase + (y0 + 3) * W, c0);
    }
}

extern "C" void kernel_launch(void* const* d_in, const int* in_sizes, int n_in,
                              void* d_out, int out_size) {
    const float* x = (const float*)d_in[0];
    float* y = (float*)d_out;
    const int nimg = in_sizes[0] / (H * W);                   // B*C images
    const int warps = nimg * (H / 4) * (W / 128);             // 128 row-quads x 4 groups
    const int threads = warps * 32;
    const int block = 128;
    const int grid = (threads + block - 1) / block;
    median3x3_kernel<<<grid, block>>>(x, y, nimg);
}

// round 9
// speedup vs baseline: 1.0947x; 1.0947x over previous
#include <cuda_runtime.h>

static constexpr int H = 512;
static constexpr int W = 512;
static constexpr unsigned FULL = 0xFFFFFFFFu;

__device__ __forceinline__ float med3f(float a, float b, float c) {
    return fmaxf(fminf(a, b), fminf(fmaxf(a, b), c));
}

// Horizontal merge for 4 outputs of one row.
// lo/md/hi: [L-edge, 4 own columns, R-edge] (6 entries), each vertically sorted.
__device__ __forceinline__ void hmerge4(const float* lo, const float* md,
                                         const float* hi, float* o) {
#pragma unroll
    for (int k = 0; k < 2; k++) {
        float pxl = fmaxf(lo[2 * k + 1], lo[2 * k + 2]);
        float pzl = fminf(hi[2 * k + 1], hi[2 * k + 2]);
        float mn  = fminf(md[2 * k + 1], md[2 * k + 2]);
        float mx  = fmaxf(md[2 * k + 1], md[2 * k + 2]);
        float X0 = fmaxf(lo[2 * k], pxl);
        float X1 = fmaxf(pxl, lo[2 * k + 3]);
        float Z0 = fminf(hi[2 * k], pzl);
        float Z1 = fminf(pzl, hi[2 * k + 3]);
        float Y0 = fmaxf(mn, fminf(mx, md[2 * k]));
        float Y1 = fmaxf(mn, fminf(mx, md[2 * k + 3]));
        o[2 * k]     = med3f(X0, Y0, Z0);
        o[2 * k + 1] = med3f(X1, Y1, Z1);
    }
}

// Merge row t into pre-sorted pair (p,q), exchange edge triples, merge, store one row.
__device__ __forceinline__ void do_row(const float* t, const float* p, const float* q,
                                        float et, float ep, float eq,
                                        bool isL, bool isR,
                                        float* __restrict__ orow, int c0) {
    float lo[6], md[6], hi[6];
#pragma unroll
    for (int i = 0; i < 4; i++) {
        float m = fmaxf(t[i], p[i]);
        lo[i + 1] = fminf(t[i], p[i]);
        hi[i + 1] = fmaxf(m, q[i]);
        md[i + 1] = fminf(m, q[i]);
    }
    float em = fmaxf(et, ep);
    float elo = fminf(et, ep), ehi = fmaxf(em, eq), emd = fminf(em, eq);
    float Ll = __shfl_up_sync(FULL, lo[4], 1);
    float Lm = __shfl_up_sync(FULL, md[4], 1);
    float Lh = __shfl_up_sync(FULL, hi[4], 1);
    float Rl = __shfl_down_sync(FULL, lo[1], 1);
    float Rm = __shfl_down_sync(FULL, md[1], 1);
    float Rh = __shfl_down_sync(FULL, hi[1], 1);
    lo[0] = isL ? elo : Ll;  md[0] = isL ? emd : Lm;  hi[0] = isL ? ehi : Lh;
    lo[5] = isR ? elo : Rl;  md[5] = isR ? emd : Rm;  hi[5] = isR ? ehi : Rh;
    float o[4];
    hmerge4(lo, md, hi, o);
    *(float4*)(orow + c0) = make_float4(o[0], o[1], o[2], o[3]);
}

// Load one tile (6 rows x 4 cols per lane + edge scalars for lanes 0/31).
// p0..p5 are per-row pointers already offset by lane*4; koff is the float offset (k*128).
__device__ __forceinline__ void load_tile(
    float4 v[6], float e[6],
    const float* p0, const float* p1, const float* p2,
    const float* p3, const float* p4, const float* p5,
    int koff, bool topOK, bool botOK, bool isL, bool isR, int c0) {
    const float4 z4 = make_float4(0.f, 0.f, 0.f, 0.f);
    v[0] = topOK ? *(const float4*)(p0 + koff) : z4;
    v[1] =         *(const float4*)(p1 + koff);
    v[2] =         *(const float4*)(p2 + koff);
    v[3] =         *(const float4*)(p3 + koff);
    v[4] =         *(const float4*)(p4 + koff);
    v[5] = botOK ? *(const float4*)(p5 + koff) : z4;
    const int eoff = isL ? -1 : 4;                       // relative to lane's c0
    const int ecol = c0 + eoff;
    const bool ev = (isL | isR) && ((unsigned)ecol < (unsigned)W);
    e[0] = (ev && topOK) ? *(p0 + koff + eoff) : 0.f;
    e[1] = ev            ? *(p1 + koff + eoff) : 0.f;
    e[2] = ev            ? *(p2 + koff + eoff) : 0.f;
    e[3] = ev            ? *(p3 + koff + eoff) : 0.f;
    e[4] = ev            ? *(p4 + koff + eoff) : 0.f;
    e[5] = (ev && botOK) ? *(p5 + koff + eoff) : 0.f;
}

// Full compute + store for one tile.
__device__ __forceinline__ void compute_tile(
    const float4 v[6], const float e[6],
    bool isL, bool isR, float* __restrict__ obase, int y0, int c0) {
    float r2[4] = {v[2].x, v[2].y, v[2].z, v[2].w};
    float r3[4] = {v[3].x, v[3].y, v[3].z, v[3].w};
    float p[4], q[4];
    {
        float r1[4] = {v[1].x, v[1].y, v[1].z, v[1].w};
#pragma unroll
        for (int i = 0; i < 4; i++) {
            p[i] = fminf(r1[i], r2[i]);
            q[i] = fmaxf(r1[i], r2[i]);
        }
    }
    {
        const float epA = fminf(e[1], e[2]), eqA = fmaxf(e[1], e[2]);
        float t0[4] = {v[0].x, v[0].y, v[0].z, v[0].w};
        do_row(t0, p, q, e[0], epA, eqA, isL, isR, obase + (y0    ) * W, c0);
        do_row(r3, p, q, e[3], epA, eqA, isL, isR, obase + (y0 + 1) * W, c0);
    }
    {
        float r4[4] = {v[4].x, v[4].y, v[4].z, v[4].w};
#pragma unroll
        for (int i = 0; i < 4; i++) {
            float mn = fminf(r3[i], r4[i]);
            float mx = fmaxf(r3[i], r4[i]);
            p[i] = mn;
            q[i] = mx;
        }
    }
    {
        const float epB = fminf(e[3], e[4]), eqB = fmaxf(e[3], e[4]);
        do_row(r2, p, q, e[2], epB, eqB, isL, isR, obase + (y0 + 2) * W, c0);
        float t5[4] = {v[5].x, v[5].y, v[5].z, v[5].w};
        do_row(t5, p, q, e[5], epB, eqB, isL, isR, obase + (y0 + 3) * W, c0);
    }
}

__global__ __launch_bounds__(128, 5)
void median3x3_kernel(const float* __restrict__ in, float* __restrict__ out, int nimg) {
    const int gwarp = (blockIdx.x * blockDim.x + threadIdx.x) >> 5;
    const int lane = threadIdx.x & 31;

    // Each warp owns one full row-quad (4 output rows x 512 cols): 4 tiles of
    // 128 cols, software-pipelined (tile k+1 loads issue before tile k compute).
    const int img = gwarp >> 7;                      // 128 quads per image
    if (img >= nimg) return;
    const int y0 = (gwarp & 127) << 2;               // 0,4,...,508
    const bool topOK = (y0 > 0);
    const bool botOK = (y0 + 4 < H);
    const bool isL = (lane == 0);
    const bool isR = (lane == 31);

    const float* __restrict__ base = in + (size_t)img * (H * W);
    float* __restrict__ obase = out + (size_t)img * (H * W);

    // Per-row pointers at this lane's column within column-group 0.
    const int lc = lane << 2;
    const float* p0 = base + (y0 - 1) * W + lc;
    const float* p1 = base + (y0    ) * W + lc;
    const float* p2 = base + (y0 + 1) * W + lc;
    const float* p3 = base + (y0 + 2) * W + lc;
    const float* p4 = base + (y0 + 3) * W + lc;
    const float* p5 = base + (y0 + 4) * W + lc;

    float4 cur[6];
    float ecur[6];
    load_tile(cur, ecur, p0, p1, p2, p3, p4, p5, 0, topOK, botOK, isL, isR, lc);

#pragma unroll
    for (int k = 0; k < 4; k++) {
        float4 nxt[6];
        float enxt[6];
        if (k < 3) {
            // Prefetch next tile BEFORE computing current one.
            load_tile(nxt, enxt, p0, p1, p2, p3, p4, p5,
                      (k + 1) * 128, topOK, botOK, isL, isR, (k + 1) * 128 + lc);
        }
        compute_tile(cur, ecur, isL, isR, obase, y0, k * 128 + lc);
        if (k < 3) {
#pragma unroll
            for (int i = 0; i < 6; i++) { cur[i] = nxt[i]; ecur[i] = enxt[i]; }
        }
    }
}

extern "C" void kernel_launch(void* const* d_in, const int* in_sizes, int n_in,
                              void* d_out, int out_size) {
    const float* x = (const float*)d_in[0];
    float* y = (float*)d_out;
    const int nimg = in_sizes[0] / (H * W);           // B*C images
    const int warps = nimg * (H / 4);                 // one warp per row-quad
    const int threads = warps * 32;
    const int block = 128;
    const int grid = (threads + block - 1) / block;
    median3x3_kernel<<<grid, block>>>(x, y, nimg);
}

// round 10
// speedup vs baseline: 1.1099x; 1.0139x over previous
#include <cuda_runtime.h>

static constexpr int H = 512;
static constexpr int W = 512;
static constexpr unsigned FULL = 0xFFFFFFFFu;

__device__ __forceinline__ float med3f(float a, float b, float c) {
    return fmaxf(fminf(a, b), fminf(fmaxf(a, b), c));
}

// Horizontal merge for 8 outputs of one row.
// lo/md/hi: [L-edge, 8 own columns, R-edge], each vertically sorted.
// Pair (2k+1, 2k+2) is shared by windows 2k and 2k+1.
__device__ __forceinline__ void hmerge8(const float* lo, const float* md,
                                         const float* hi, float* o) {
#pragma unroll
    for (int k = 0; k < 4; k++) {
        float pxl = fmaxf(lo[2 * k + 1], lo[2 * k + 2]);
        float pzl = fminf(hi[2 * k + 1], hi[2 * k + 2]);
        float mn  = fminf(md[2 * k + 1], md[2 * k + 2]);
        float mx  = fmaxf(md[2 * k + 1], md[2 * k + 2]);
        float X0 = fmaxf(lo[2 * k], pxl);
        float X1 = fmaxf(pxl, lo[2 * k + 3]);
        float Z0 = fminf(hi[2 * k], pzl);
        float Z1 = fminf(pzl, hi[2 * k + 3]);
        float Y0 = fmaxf(mn, fminf(mx, md[2 * k]));
        float Y1 = fmaxf(mn, fminf(mx, md[2 * k + 3]));
        o[2 * k]     = med3f(X0, Y0, Z0);
        o[2 * k + 1] = med3f(X1, Y1, Z1);
    }
}

// Merge row t into pre-sorted pair (p,q), exchange edge triples, merge, store one row.
__device__ __forceinline__ void do_row(const float* t, const float* p, const float* q,
                                        float et, float ep, float eq,
                                        bool isL, bool isR,
                                        float* __restrict__ orow, int c0) {
    float lo[10], md[10], hi[10];
#pragma unroll
    for (int i = 0; i < 8; i++) {
        float m = fmaxf(t[i], p[i]);
        lo[i + 1] = fminf(t[i], p[i]);
        hi[i + 1] = fmaxf(m, q[i]);
        md[i + 1] = fminf(m, q[i]);
    }
    float em = fmaxf(et, ep);
    float elo = fminf(et, ep), ehi = fmaxf(em, eq), emd = fminf(em, eq);
    float Ll = __shfl_up_sync(FULL, lo[8], 1);
    float Lm = __shfl_up_sync(FULL, md[8], 1);
    float Lh = __shfl_up_sync(FULL, hi[8], 1);
    float Rl = __shfl_down_sync(FULL, lo[1], 1);
    float Rm = __shfl_down_sync(FULL, md[1], 1);
    float Rh = __shfl_down_sync(FULL, hi[1], 1);
    lo[0] = isL ? elo : Ll;  md[0] = isL ? emd : Lm;  hi[0] = isL ? ehi : Lh;
    lo[9] = isR ? elo : Rl;  md[9] = isR ? emd : Rm;  hi[9] = isR ? ehi : Rh;
    float o[8];
    hmerge8(lo, md, hi, o);
    *(float4*)(orow + c0)     = make_float4(o[0], o[1], o[2], o[3]);
    *(float4*)(orow + c0 + 4) = make_float4(o[4], o[5], o[6], o[7]);
}

// Load one 256-col tile: 6 rows x 8 cols per lane (12 LDG.128) + edge scalars.
__device__ __forceinline__ void load_tile(
    float4 v[12], float e[6],
    const float* p0, const float* p1, const float* p2,
    const float* p3, const float* p4, const float* p5,
    int koff, bool topOK, bool botOK, bool isL, bool isR, int c0) {
    const float4 z4 = make_float4(0.f, 0.f, 0.f, 0.f);
    v[0]  = topOK ? *(const float4*)(p0 + koff)     : z4;
    v[1]  = topOK ? *(const float4*)(p0 + koff + 4) : z4;
    v[2]  =         *(const float4*)(p1 + koff);
    v[3]  =         *(const float4*)(p1 + koff + 4);
    v[4]  =         *(const float4*)(p2 + koff);
    v[5]  =         *(const float4*)(p2 + koff + 4);
    v[6]  =         *(const float4*)(p3 + koff);
    v[7]  =         *(const float4*)(p3 + koff + 4);
    v[8]  =         *(const float4*)(p4 + koff);
    v[9]  =         *(const float4*)(p4 + koff + 4);
    v[10] = botOK ? *(const float4*)(p5 + koff)     : z4;
    v[11] = botOK ? *(const float4*)(p5 + koff + 4) : z4;
    const int eoff = isL ? -1 : 8;                    // relative to lane's column base
    const int ecol = c0 + eoff;
    const bool ev = (isL | isR) && ((unsigned)ecol < (unsigned)W);
    e[0] = (ev && topOK) ? *(p0 + koff + eoff) : 0.f;
    e[1] = ev            ? *(p1 + koff + eoff) : 0.f;
    e[2] = ev            ? *(p2 + koff + eoff) : 0.f;
    e[3] = ev            ? *(p3 + koff + eoff) : 0.f;
    e[4] = ev            ? *(p4 + koff + eoff) : 0.f;
    e[5] = (ev && botOK) ? *(p5 + koff + eoff) : 0.f;
}

// Full compute + store for one 256-col tile (R5 network).
__device__ __forceinline__ void compute_tile(
    const float4 v[12], const float e[6],
    bool isL, bool isR, float* __restrict__ obase, int y0, int c0) {
    float r2[8] = {v[4].x, v[4].y, v[4].z, v[4].w, v[5].x, v[5].y, v[5].z, v[5].w};
    float r3[8] = {v[6].x, v[6].y, v[6].z, v[6].w, v[7].x, v[7].y, v[7].z, v[7].w};

    float p[8], q[8];
    {
        float r1[8] = {v[2].x, v[2].y, v[2].z, v[2].w, v[3].x, v[3].y, v[3].z, v[3].w};
#pragma unroll
        for (int i = 0; i < 8; i++) {
            p[i] = fminf(r1[i], r2[i]);
            q[i] = fmaxf(r1[i], r2[i]);
        }
    }
    {
        const float epA = fminf(e[1], e[2]), eqA = fmaxf(e[1], e[2]);
        float t0[8] = {v[0].x, v[0].y, v[0].z, v[0].w, v[1].x, v[1].y, v[1].z, v[1].w};
        do_row(t0, p, q, e[0], epA, eqA, isL, isR, obase + (y0    ) * W, c0);
        do_row(r3, p, q, e[3], epA, eqA, isL, isR, obase + (y0 + 1) * W, c0);
    }
    {
        float r4[8] = {v[8].x, v[8].y, v[8].z, v[8].w, v[9].x, v[9].y, v[9].z, v[9].w};
#pragma unroll
        for (int i = 0; i < 8; i++) {
            float mn = fminf(r3[i], r4[i]);
            float mx = fmaxf(r3[i], r4[i]);
            p[i] = mn;
            q[i] = mx;
        }
    }
    {
        const float epB = fminf(e[3], e[4]), eqB = fmaxf(e[3], e[4]);
        do_row(r2, p, q, e[2], epB, eqB, isL, isR, obase + (y0 + 2) * W, c0);
        float t5[8] = {v[10].x, v[10].y, v[10].z, v[10].w, v[11].x, v[11].y, v[11].z, v[11].w};
        do_row(t5, p, q, e[5], epB, eqB, isL, isR, obase + (y0 + 3) * W, c0);
    }
}

__global__ __launch_bounds__(128, 4)
void median3x3_kernel(const float* __restrict__ in, float* __restrict__ out, int nimg) {
    const int gwarp = (blockIdx.x * blockDim.x + threadIdx.x) >> 5;
    const int lane = threadIdx.x & 31;

    // Each warp owns one full row-quad (4 output rows x 512 cols): 2 tiles of
    // 256 cols (8 cols/lane), software-pipelined.
    const int img = gwarp >> 7;                      // 128 quads per image
    if (img >= nimg) return;
    const int y0 = (gwarp & 127) << 2;               // 0,4,...,508
    const bool topOK = (y0 > 0);
    const bool botOK = (y0 + 4 < H);
    const bool isL = (lane == 0);
    const bool isR = (lane == 31);

    const float* __restrict__ base = in + (size_t)img * (H * W);
    float* __restrict__ obase = out + (size_t)img * (H * W);

    const int lc = lane << 3;                        // 8 cols per lane
    const float* p0 = base + (y0 - 1) * W + lc;
    const float* p1 = base + (y0    ) * W + lc;
    const float* p2 = base + (y0 + 1) * W + lc;
    const float* p3 = base + (y0 + 2) * W + lc;
    const float* p4 = base + (y0 + 3) * W + lc;
    const float* p5 = base + (y0 + 4) * W + lc;

    float4 cur[12];
    float ecur[6];
    load_tile(cur, ecur, p0, p1, p2, p3, p4, p5, 0, topOK, botOK, isL, isR, lc);

    // Prefetch tile 1 BEFORE computing tile 0 — the ~500 alu ops of tile 0
    // cover tile 1's DRAM latency.
    float4 nxt[12];
    float enxt[6];
    load_tile(nxt, enxt, p0, p1, p2, p3, p4, p5, 256, topOK, botOK, isL, isR, 256 + lc);

    compute_tile(cur, ecur, isL, isR, obase, y0, lc);
    compute_tile(nxt, enxt, isL, isR, obase, y0, 256 + lc);
}

extern "C" void kernel_launch(void* const* d_in, const int* in_sizes, int n_in,
                              void* d_out, int out_size) {
    const float* x = (const float*)d_in[0];
    float* y = (float*)d_out;
    const int nimg = in_sizes[0] / (H * W);           // B*C images
    const int warps = nimg * (H / 4);                 // one warp per row-quad
    const int threads = warps * 32;
    const int block = 128;
    const int grid = (threads + block - 1) / block;
    median3x3_kernel<<<grid, block>>>(x, y, nimg);
}